// round 9
// baseline (speedup 1.0000x reference)
#include <cuda_runtime.h>
#include <math.h>

#define BB   4
#define CC   16
#define TT   1000
#define FF   96
#define HH   64
#define HID  1536
#define IND  6144
#define G3   4608

// persistent-GRU geometry: 128 blocks x 12 warps = 1536 = HID j-slots
#define GRU_BLOCKS 128
#define GRU_THREADS 384

// ---- scratch (device globals: no allocation allowed) ----
__device__ __align__(16) float g_seq[(size_t)BB * TT * IND];  // [B*T][6144]
__device__ __align__(16) float g_gx [(size_t)BB * TT * G3];   // [B*T][4608]
__device__ __align__(16) float g_h  [2][BB * HID];            // double-buffered GRU state

// ---- software grid barrier state (reset by k_init every replay) ----
__device__ int          g_cnt[8 * 32];   // 8 group counters, 128B apart
__device__ int          g_master;
__device__ volatile int g_epoch;

// =====================================================================
// init: copy h0 into g_h[0]; reset barrier state
// =====================================================================
__global__ void k_init(const float* __restrict__ h0) {
    int i = blockIdx.x * blockDim.x + threadIdx.x;
    if (i < BB * HID) g_h[0][i] = h0[i];
    if (i < 8 * 32) g_cnt[i] = 0;
    if (i == 0) { g_master = 0; g_epoch = 0; }
}

// =====================================================================
// fused conv(1x3) q/k/v + per-(b,t) joint-2D-softmax attention
// one CTA per (b,t); 256 threads; everything in shared memory
// writes seq[b*T+t][f*64+h] = a[f][h]
// =====================================================================
__global__ __launch_bounds__(256) void k_attn(
    const float* __restrict__ x,
    const float* __restrict__ Wq, const float* __restrict__ bq,
    const float* __restrict__ Wk, const float* __restrict__ bk,
    const float* __restrict__ Wv, const float* __restrict__ bv)
{
    extern __shared__ float sm[];
    float* xs  = sm;              // 16*98 (halo-padded along f)
    float* wq  = xs  + 16 * 98;   // 3072 = 64*16*3
    float* wk  = wq  + 3072;
    float* wv  = wk  + 3072;
    float* bqs = wv  + 3072;      // 64
    float* bks = bqs + 64;
    float* bvs = bks + 64;
    float* qs  = bvs + 64;        // 64*97 (pad to kill bank conflicts)
    float* ks  = qs  + 64 * 97;
    float* vs  = ks  + 64 * 97;
    float* ss  = vs  + 64 * 97;   // 96*96 scores
    __shared__ float red[16];

    const int tid = threadIdx.x;
    const int t = blockIdx.x, b = blockIdx.y;

    // ---- load conv weights/biases ----
    for (int i = tid; i < 3072; i += 256) { wq[i] = Wq[i]; wk[i] = Wk[i]; wv[i] = Wv[i]; }
    if (tid < 64) { bqs[tid] = bq[tid]; bks[tid] = bk[tid]; bvs[tid] = bv[tid]; }

    // ---- load x tile [16][96] with zero halo ----
    for (int i = tid; i < CC * FF; i += 256) {
        int c = i / FF, f = i - c * FF;
        xs[c * 98 + f + 1] = x[(((size_t)b * CC + c) * TT + t) * FF + f];
    }
    if (tid < 2 * CC) { int c = tid >> 1; xs[c * 98 + ((tid & 1) ? 97 : 0)] = 0.f; }
    __syncthreads();

    // ---- conv -> q,k,v [64][96] ----
    for (int e = tid; e < HH * FF; e += 256) {
        int h = e / FF, f = e - h * FF;
        float aq = bqs[h], ak = bks[h], av = bvs[h];
        const float* wqr = wq + h * 48;
        const float* wkr = wk + h * 48;
        const float* wvr = wv + h * 48;
        #pragma unroll 4
        for (int c = 0; c < CC; c++) {
            float x0 = xs[c * 98 + f], x1 = xs[c * 98 + f + 1], x2 = xs[c * 98 + f + 2];
            aq += x0 * wqr[c * 3] + x1 * wqr[c * 3 + 1] + x2 * wqr[c * 3 + 2];
            ak += x0 * wkr[c * 3] + x1 * wkr[c * 3 + 1] + x2 * wkr[c * 3 + 2];
            av += x0 * wvr[c * 3] + x1 * wvr[c * 3 + 1] + x2 * wvr[c * 3 + 2];
        }
        qs[h * 97 + f] = aq; ks[h * 97 + f] = ak; vs[h * 97 + f] = av;
    }
    __syncthreads();

    // ---- S[f][g] = (1/8) sum_h q[h][f] k[h][g]  (2x2 tiles/thread) ----
    for (int e = tid; e < 2304; e += 256) {
        int f0 = e / 48, g0 = e - f0 * 48;
        float a00 = 0.f, a01 = 0.f, a10 = 0.f, a11 = 0.f;
        #pragma unroll 4
        for (int h = 0; h < HH; h++) {
            float q0 = qs[h * 97 + f0], q1 = qs[h * 97 + f0 + 48];
            float k0 = ks[h * 97 + g0], k1 = ks[h * 97 + g0 + 48];
            a00 += q0 * k0; a01 += q0 * k1; a10 += q1 * k0; a11 += q1 * k1;
        }
        ss[f0 * 96 + g0]             = a00 * 0.125f;
        ss[f0 * 96 + g0 + 48]        = a01 * 0.125f;
        ss[(f0 + 48) * 96 + g0]      = a10 * 0.125f;
        ss[(f0 + 48) * 96 + g0 + 48] = a11 * 0.125f;
    }
    __syncthreads();

    // ---- joint 2D softmax over all 9216 scores ----
    float m = -1e30f;
    for (int e = tid; e < 9216; e += 256) m = fmaxf(m, ss[e]);
    #pragma unroll
    for (int off = 16; off; off >>= 1) m = fmaxf(m, __shfl_xor_sync(0xffffffffu, m, off));
    if ((tid & 31) == 0) red[tid >> 5] = m;
    __syncthreads();
    if (tid == 0) { float mm = red[0]; for (int i = 1; i < 8; i++) mm = fmaxf(mm, red[i]); red[0] = mm; }
    __syncthreads();
    const float M = red[0];

    float s = 0.f;
    for (int e = tid; e < 9216; e += 256) { float v = expf(ss[e] - M); ss[e] = v; s += v; }
    #pragma unroll
    for (int off = 16; off; off >>= 1) s += __shfl_xor_sync(0xffffffffu, s, off);
    if ((tid & 31) == 0) red[8 + (tid >> 5)] = s;
    __syncthreads();
    if (tid == 0) { float tt = 0.f; for (int i = 0; i < 8; i++) tt += red[8 + i]; red[8] = 1.0f / tt; }
    __syncthreads();
    const float inv = red[8];

    // ---- a[f][h] = inv * sum_g w[f][g] v[h][g]  (2x2 tiles/thread) ----
    float* seqp = g_seq + (size_t)(b * TT + t) * IND;
    for (int e = tid; e < 1536; e += 256) {
        int f0 = e >> 5, h0 = e & 31;      // f0 0..47 (+48), h0 0..31 (+32)
        float a00 = 0.f, a01 = 0.f, a10 = 0.f, a11 = 0.f;
        #pragma unroll 4
        for (int g = 0; g < 96; g++) {
            float s0 = ss[f0 * 96 + g], s1 = ss[(f0 + 48) * 96 + g];
            float v0 = vs[h0 * 97 + g], v1 = vs[(h0 + 32) * 97 + g];
            a00 += s0 * v0; a01 += s0 * v1; a10 += s1 * v0; a11 += s1 * v1;
        }
        seqp[f0 * 64 + h0]              = a00 * inv;
        seqp[f0 * 64 + h0 + 32]         = a01 * inv;
        seqp[(f0 + 48) * 64 + h0]       = a10 * inv;
        seqp[(f0 + 48) * 64 + h0 + 32]  = a11 * inv;
    }
}

// =====================================================================
// gx = seq @ Wih^T + bih : [4000,6144] x [4608,6144]^T -> [4000,4608]
// fp32 SIMT, 128x128x16 tiles, 8x8 per thread, 256 threads
// =====================================================================
#define GBM 128
#define GBN 128
#define GBK 16
__global__ __launch_bounds__(256, 2) void k_gemm(
    const float* __restrict__ Wih, const float* __restrict__ bih)
{
    __shared__ __align__(16) float As[GBK][GBM + 4];
    __shared__ __align__(16) float Bs[GBK][GBN + 4];
    const int tid = threadIdx.x;
    const int bm = blockIdx.y * GBM;
    const int bn = blockIdx.x * GBN;
    const int lr = tid >> 1;            // 0..127 : row within tile
    const int lk = (tid & 1) * 8;       // 0 or 8 : k offset
    const int tx = tid & 15, ty = tid >> 4;

    float acc[8][8];
    #pragma unroll
    for (int i = 0; i < 8; i++)
        #pragma unroll
        for (int j = 0; j < 8; j++) acc[i][j] = 0.f;

    const bool  avalid = (bm + lr) < (BB * TT);
    const float* Arow = g_seq + (size_t)(bm + lr) * IND;
    const float* Brow = Wih   + (size_t)(bn + lr) * IND;

    for (int k0 = 0; k0 < IND; k0 += GBK) {
        float4 a0, a1;
        if (avalid) {
            a0 = *(const float4*)(Arow + k0 + lk);
            a1 = *(const float4*)(Arow + k0 + lk + 4);
        } else { a0 = make_float4(0.f,0.f,0.f,0.f); a1 = a0; }
        float4 b0 = *(const float4*)(Brow + k0 + lk);
        float4 b1 = *(const float4*)(Brow + k0 + lk + 4);

        As[lk + 0][lr] = a0.x; As[lk + 1][lr] = a0.y; As[lk + 2][lr] = a0.z; As[lk + 3][lr] = a0.w;
        As[lk + 4][lr] = a1.x; As[lk + 5][lr] = a1.y; As[lk + 6][lr] = a1.z; As[lk + 7][lr] = a1.w;
        Bs[lk + 0][lr] = b0.x; Bs[lk + 1][lr] = b0.y; Bs[lk + 2][lr] = b0.z; Bs[lk + 3][lr] = b0.w;
        Bs[lk + 4][lr] = b1.x; Bs[lk + 5][lr] = b1.y; Bs[lk + 6][lr] = b1.z; Bs[lk + 7][lr] = b1.w;
        __syncthreads();

        #pragma unroll
        for (int kk = 0; kk < GBK; kk++) {
            float4 fa0 = *(const float4*)&As[kk][ty * 4];
            float4 fa1 = *(const float4*)&As[kk][64 + ty * 4];
            float4 fb0 = *(const float4*)&Bs[kk][tx * 4];
            float4 fb1 = *(const float4*)&Bs[kk][64 + tx * 4];
            float av[8] = {fa0.x, fa0.y, fa0.z, fa0.w, fa1.x, fa1.y, fa1.z, fa1.w};
            float bv[8] = {fb0.x, fb0.y, fb0.z, fb0.w, fb1.x, fb1.y, fb1.z, fb1.w};
            #pragma unroll
            for (int i = 0; i < 8; i++)
                #pragma unroll
                for (int j = 0; j < 8; j++)
                    acc[i][j] += av[i] * bv[j];
        }
        __syncthreads();
    }

    #pragma unroll
    for (int i = 0; i < 8; i++) {
        int m = bm + ((i < 4) ? (ty * 4 + i) : (64 + ty * 4 + i - 4));
        if (m >= BB * TT) continue;
        float* crow = g_gx + (size_t)m * G3;
        #pragma unroll
        for (int j = 0; j < 8; j++) {
            int n = bn + ((j < 4) ? (tx * 4 + j) : (64 + tx * 4 + j - 4));
            crow[n] = acc[i][j] + bih[n];
        }
    }
}

// =====================================================================
// software grid barrier: two-level (8 group counters -> master -> epoch)
// all GRU blocks are co-resident (128 blocks <= 148 SMs), so spinning is safe
// =====================================================================
__device__ __forceinline__ void grid_barrier(int e, int bid) {
    __syncthreads();                       // all block stores issued (cumulative with fence below)
    if (threadIdx.x == 0) {
        __threadfence();                   // publish this block's h writes device-wide
        int g = (bid & 7) * 32;
        int v = atomicAdd(&g_cnt[g], 1);
        if (v == (GRU_BLOCKS / 8) - 1) {   // 16th arrival in this group
            atomicExch(&g_cnt[g], 0);
            int m = atomicAdd(&g_master, 1);
            if (m == 7) {                  // last group
                atomicExch(&g_master, 0);
                __threadfence();
                g_epoch = e;               // release
            }
        }
        while (g_epoch < e) { }            // acquire via spin
        __threadfence();
    }
    __syncthreads();
}

// =====================================================================
// persistent GRU: ONE kernel for all 1000 timesteps.
// 128 blocks x 384 threads; warp per j (12 j's/block), all 4 batches/warp.
// Whh read once per step from L2; h broadcast via global + smem stage.
// =====================================================================
__global__ __launch_bounds__(GRU_THREADS, 1) void k_gru_persist(
    const float* __restrict__ Whh, const float* __restrict__ bhh,
    const float* __restrict__ gx, float* __restrict__ out)
{
    __shared__ __align__(16) float hs[BB * HID];   // 24 KB: full h state

    const int tid = threadIdx.x;
    const int lane = tid & 31, warp = tid >> 5;
    const int bid = blockIdx.x;
    const int j = bid * 12 + warp;                 // 0..1535

    const float4* wr = (const float4*)(Whh + (size_t)j * HID);
    const float4* wz = (const float4*)(Whh + (size_t)(HID + j) * HID);
    const float4* wn = (const float4*)(Whh + (size_t)(2 * HID + j) * HID);
    const float bhr = bhh[j], bhz = bhh[HID + j], bhn = bhh[2 * HID + j];
    const int c = j / FF, f = j - c * FF;

    for (int t = 0; t < TT; t++) {
        // stage h_{t-1} into smem (4 float4 loads per thread)
        const float4* hp4 = (const float4*)g_h[t & 1];
        float4* hs4 = (float4*)hs;
        #pragma unroll
        for (int i = 0; i < 4; i++) hs4[tid + i * GRU_THREADS] = hp4[tid + i * GRU_THREADS];
        __syncthreads();

        float ar[4] = {0.f,0.f,0.f,0.f};
        float az[4] = {0.f,0.f,0.f,0.f};
        float an[4] = {0.f,0.f,0.f,0.f};

        #pragma unroll 4
        for (int k = lane; k < HID / 4; k += 32) {
            float4 r4 = wr[k], z4 = wz[k], n4 = wn[k];
            #pragma unroll
            for (int b = 0; b < 4; b++) {
                float4 h4 = hs4[b * (HID / 4) + k];
                ar[b] += r4.x * h4.x + r4.y * h4.y + r4.z * h4.z + r4.w * h4.w;
                az[b] += z4.x * h4.x + z4.y * h4.y + z4.z * h4.z + z4.w * h4.w;
                an[b] += n4.x * h4.x + n4.y * h4.y + n4.z * h4.z + n4.w * h4.w;
            }
        }
        #pragma unroll
        for (int off = 16; off; off >>= 1) {
            #pragma unroll
            for (int b = 0; b < 4; b++) {
                ar[b] += __shfl_xor_sync(0xffffffffu, ar[b], off);
                az[b] += __shfl_xor_sync(0xffffffffu, az[b], off);
                an[b] += __shfl_xor_sync(0xffffffffu, an[b], off);
            }
        }

        if (lane < 4) {
            const int b = lane;
            float sr, sz, sn;
            if      (b == 0) { sr = ar[0]; sz = az[0]; sn = an[0]; }
            else if (b == 1) { sr = ar[1]; sz = az[1]; sn = an[1]; }
            else if (b == 2) { sr = ar[2]; sz = az[2]; sn = an[2]; }
            else             { sr = ar[3]; sz = az[3]; sn = an[3]; }

            float ghr = sr + bhr;
            float ghz = sz + bhz;
            float ghn = sn + bhn;

            size_t gxb = ((size_t)b * TT + t) * G3;
            float r = 1.f / (1.f + expf(-(gx[gxb + j]           + ghr)));
            float z = 1.f / (1.f + expf(-(gx[gxb + HID + j]     + ghz)));
            float n = tanhf(      gx[gxb + 2 * HID + j] + r * ghn);
            float hp = hs[b * HID + j];
            float hn = (1.f - z) * n + z * hp;

            g_h[(t + 1) & 1][b * HID + j] = hn;
            out[(((size_t)b * CC + c) * TT + t) * FF + f] = hn;   // o[b][c][t][f]
            if (t == TT - 1) out[(size_t)BB * CC * TT * FF + b * HID + j] = hn;  // hT tail
        }

        grid_barrier(t + 1, bid);
    }
}

// =====================================================================
extern "C" void kernel_launch(void* const* d_in, const int* in_sizes, int n_in,
                              void* d_out, int out_size)
{
    const float* x   = (const float*)d_in[0];
    const float* h0  = (const float*)d_in[1];
    const float* Wq  = (const float*)d_in[2];
    const float* bq  = (const float*)d_in[3];
    const float* Wk  = (const float*)d_in[4];
    const float* bk  = (const float*)d_in[5];
    const float* Wv  = (const float*)d_in[6];
    const float* bv  = (const float*)d_in[7];
    const float* Wih = (const float*)d_in[8];
    const float* Whh = (const float*)d_in[9];
    const float* bih = (const float*)d_in[10];
    const float* bhh = (const float*)d_in[11];
    float* out = (float*)d_out;

    const int smem_attn = 38816 * (int)sizeof(float);   // ~152 KB < 227 KB cap
    cudaFuncSetAttribute(k_attn, cudaFuncAttributeMaxDynamicSharedMemorySize, smem_attn);

    float* gxp = nullptr;
    cudaGetSymbolAddress((void**)&gxp, g_gx);

    // 4 graph nodes total (vs 1002): kills the 2 MB graph-upload residual
    k_init<<<(BB * HID + 255) / 256, 256>>>(h0);
    k_attn<<<dim3(TT, BB), 256, smem_attn>>>(x, Wq, bq, Wk, bk, Wv, bv);
    k_gemm<<<dim3(G3 / GBN, (BB * TT + GBM - 1) / GBM), 256>>>(Wih, bih);
    k_gru_persist<<<GRU_BLOCKS, GRU_THREADS>>>(Whh, bhh, gxp, out);
}

// round 11
// speedup vs baseline: 1.3409x; 1.3409x over previous
#include <cuda_runtime.h>
#include <stdint.h>
#include <math.h>

#define BB   4
#define CC   16
#define TT   1000
#define FF   96
#define HH   64
#define HID  1536
#define IND  6144
#define G3   4608

// persistent-GRU geometry: 128 blocks x 12 warps = 1536 = HID j-slots
#define GRU_BLOCKS 128
#define GRU_THREADS 384

// ---- scratch (device globals: no allocation allowed) ----
__device__ __align__(16) float g_seq[(size_t)BB * TT * IND];   // [B*T][6144] (tf32-rounded)
__device__ __align__(16) float g_gx [(size_t)BB * TT * G3];    // [B*T][4608]
__device__ __align__(16) float g_h  [2][BB * HID];             // double-buffered GRU state
__device__ __align__(16) float g_wih32[(size_t)G3 * IND];      // tf32-rounded Wih copy

// ---- software grid barrier state (reset by k_init every replay) ----
__device__ int          g_cnt[8 * 32];
__device__ int          g_master;
__device__ volatile int g_epoch;

__device__ __forceinline__ unsigned int f2tf32(float x) {
    unsigned int r; asm("cvt.rna.tf32.f32 %0, %1;" : "=r"(r) : "f"(x)); return r;
}

// =====================================================================
// init: copy h0 into g_h[0]; reset barrier state
// =====================================================================
__global__ void k_init(const float* __restrict__ h0) {
    int i = blockIdx.x * blockDim.x + threadIdx.x;
    if (i < BB * HID) g_h[0][i] = h0[i];
    if (i < 8 * 32) g_cnt[i] = 0;
    if (i == 0) { g_master = 0; g_epoch = 0; }
}

// =====================================================================
// round Wih -> tf32 (one-time per replay; ~113MB streaming, ~30us)
// =====================================================================
__global__ void k_cvt(const float* __restrict__ Wih) {
    const size_t n4 = (size_t)G3 * IND / 4;
    const float4* src = (const float4*)Wih;
    float4* dst = (float4*)g_wih32;
    for (size_t i = (size_t)blockIdx.x * blockDim.x + threadIdx.x; i < n4;
         i += (size_t)gridDim.x * blockDim.x) {
        float4 v = src[i];
        v.x = __uint_as_float(f2tf32(v.x));
        v.y = __uint_as_float(f2tf32(v.y));
        v.z = __uint_as_float(f2tf32(v.z));
        v.w = __uint_as_float(f2tf32(v.w));
        dst[i] = v;
    }
}

// =====================================================================
// fused conv(1x3) q/k/v + per-(b,t) joint-2D-softmax attention
// one CTA per (b,t); 256 threads; everything in shared memory
// writes seq[b*T+t][f*64+h] = a[f][h]  (tf32-rounded: feeds tensor GEMM only)
// =====================================================================
__global__ __launch_bounds__(256) void k_attn(
    const float* __restrict__ x,
    const float* __restrict__ Wq, const float* __restrict__ bq,
    const float* __restrict__ Wk, const float* __restrict__ bk,
    const float* __restrict__ Wv, const float* __restrict__ bv)
{
    extern __shared__ float sm[];
    float* xs  = sm;              // 16*98 (halo-padded along f)
    float* wq  = xs  + 16 * 98;   // 3072 = 64*16*3
    float* wk  = wq  + 3072;
    float* wv  = wk  + 3072;
    float* bqs = wv  + 3072;      // 64
    float* bks = bqs + 64;
    float* bvs = bks + 64;
    float* qs  = bvs + 64;        // 64*97 (pad to kill bank conflicts)
    float* ks  = qs  + 64 * 97;
    float* vs  = ks  + 64 * 97;
    float* ss  = vs  + 64 * 97;   // 96*96 scores
    __shared__ float red[16];

    const int tid = threadIdx.x;
    const int t = blockIdx.x, b = blockIdx.y;

    for (int i = tid; i < 3072; i += 256) { wq[i] = Wq[i]; wk[i] = Wk[i]; wv[i] = Wv[i]; }
    if (tid < 64) { bqs[tid] = bq[tid]; bks[tid] = bk[tid]; bvs[tid] = bv[tid]; }

    for (int i = tid; i < CC * FF; i += 256) {
        int c = i / FF, f = i - c * FF;
        xs[c * 98 + f + 1] = x[(((size_t)b * CC + c) * TT + t) * FF + f];
    }
    if (tid < 2 * CC) { int c = tid >> 1; xs[c * 98 + ((tid & 1) ? 97 : 0)] = 0.f; }
    __syncthreads();

    for (int e = tid; e < HH * FF; e += 256) {
        int h = e / FF, f = e - h * FF;
        float aq = bqs[h], ak = bks[h], av = bvs[h];
        const float* wqr = wq + h * 48;
        const float* wkr = wk + h * 48;
        const float* wvr = wv + h * 48;
        #pragma unroll 4
        for (int c = 0; c < CC; c++) {
            float x0 = xs[c * 98 + f], x1 = xs[c * 98 + f + 1], x2 = xs[c * 98 + f + 2];
            aq += x0 * wqr[c * 3] + x1 * wqr[c * 3 + 1] + x2 * wqr[c * 3 + 2];
            ak += x0 * wkr[c * 3] + x1 * wkr[c * 3 + 1] + x2 * wkr[c * 3 + 2];
            av += x0 * wvr[c * 3] + x1 * wvr[c * 3 + 1] + x2 * wvr[c * 3 + 2];
        }
        qs[h * 97 + f] = aq; ks[h * 97 + f] = ak; vs[h * 97 + f] = av;
    }
    __syncthreads();

    for (int e = tid; e < 2304; e += 256) {
        int f0 = e / 48, g0 = e - f0 * 48;
        float a00 = 0.f, a01 = 0.f, a10 = 0.f, a11 = 0.f;
        #pragma unroll 4
        for (int h = 0; h < HH; h++) {
            float q0 = qs[h * 97 + f0], q1 = qs[h * 97 + f0 + 48];
            float k0 = ks[h * 97 + g0], k1 = ks[h * 97 + g0 + 48];
            a00 += q0 * k0; a01 += q0 * k1; a10 += q1 * k0; a11 += q1 * k1;
        }
        ss[f0 * 96 + g0]             = a00 * 0.125f;
        ss[f0 * 96 + g0 + 48]        = a01 * 0.125f;
        ss[(f0 + 48) * 96 + g0]      = a10 * 0.125f;
        ss[(f0 + 48) * 96 + g0 + 48] = a11 * 0.125f;
    }
    __syncthreads();

    float m = -1e30f;
    for (int e = tid; e < 9216; e += 256) m = fmaxf(m, ss[e]);
    #pragma unroll
    for (int off = 16; off; off >>= 1) m = fmaxf(m, __shfl_xor_sync(0xffffffffu, m, off));
    if ((tid & 31) == 0) red[tid >> 5] = m;
    __syncthreads();
    if (tid == 0) { float mm = red[0]; for (int i = 1; i < 8; i++) mm = fmaxf(mm, red[i]); red[0] = mm; }
    __syncthreads();
    const float M = red[0];

    float s = 0.f;
    for (int e = tid; e < 9216; e += 256) { float v = expf(ss[e] - M); ss[e] = v; s += v; }
    #pragma unroll
    for (int off = 16; off; off >>= 1) s += __shfl_xor_sync(0xffffffffu, s, off);
    if ((tid & 31) == 0) red[8 + (tid >> 5)] = s;
    __syncthreads();
    if (tid == 0) { float tt = 0.f; for (int i = 0; i < 8; i++) tt += red[8 + i]; red[8] = 1.0f / tt; }
    __syncthreads();
    const float inv = red[8];

    float* seqp = g_seq + (size_t)(b * TT + t) * IND;
    for (int e = tid; e < 1536; e += 256) {
        int f0 = e >> 5, h0 = e & 31;
        float a00 = 0.f, a01 = 0.f, a10 = 0.f, a11 = 0.f;
        #pragma unroll 4
        for (int g = 0; g < 96; g++) {
            float s0 = ss[f0 * 96 + g], s1 = ss[(f0 + 48) * 96 + g];
            float v0 = vs[h0 * 97 + g], v1 = vs[(h0 + 32) * 97 + g];
            a00 += s0 * v0; a01 += s0 * v1; a10 += s1 * v0; a11 += s1 * v1;
        }
        seqp[f0 * 64 + h0]             = __uint_as_float(f2tf32(a00 * inv));
        seqp[f0 * 64 + h0 + 32]        = __uint_as_float(f2tf32(a01 * inv));
        seqp[(f0 + 48) * 64 + h0]      = __uint_as_float(f2tf32(a10 * inv));
        seqp[(f0 + 48) * 64 + h0 + 32] = __uint_as_float(f2tf32(a11 * inv));
    }
}

// =====================================================================
// tf32 tensor-core GEMM: gx = seq @ Wih^T + bih
// [4000,6144] x [4608,6144]^T -> [4000,4608]
// 128x128x32 tiles, 8 warps (2x4), warp tile 64x32, mma.m16n8k8.tf32,
// 2-stage cp.async pipeline. Operands pre-rounded to tf32 in gmem.
// =====================================================================
#define TLEN 36                       // padded row stride (floats): conflict-free
#define TBUF (128 * TLEN)             // 4608 floats per tile buffer

__device__ __forceinline__ void cp16(unsigned int dst, const float* src) {
    asm volatile("cp.async.cg.shared.global [%0], [%1], 16;" :: "r"(dst), "l"(src));
}

__global__ __launch_bounds__(256) void k_gemm_t32(const float* __restrict__ bih)
{
    extern __shared__ float smx[];
    float* As = smx;                  // [2][TBUF]
    float* Bs = smx + 2 * TBUF;       // [2][TBUF]

    const int tid  = threadIdx.x;
    const int bm   = blockIdx.y * 128;
    const int bn   = blockIdx.x * 128;
    const int w    = tid >> 5;
    const int lane = tid & 31;
    const int wm   = (w & 1) * 64;
    const int wn   = (w >> 1) * 32;
    const int gid  = lane >> 2;       // 0..7
    const int tig  = lane & 3;        // 0..3

    const unsigned int sA = (unsigned int)__cvta_generic_to_shared(As);
    const unsigned int sB = (unsigned int)__cvta_generic_to_shared(Bs);

    // per-thread load coords (4 x float4 per tile per matrix)
    int lrow[4], lcol[4];
    #pragma unroll
    for (int j = 0; j < 4; j++) {
        int idx = tid + j * 256;
        lrow[j] = idx >> 3;
        lcol[j] = (idx & 7) * 4;
    }
    const float* aptr[4]; const float* bptr[4];
    #pragma unroll
    for (int j = 0; j < 4; j++) {
        int am = bm + lrow[j]; if (am > BB * TT - 1) am = BB * TT - 1;  // clamp (stores guarded)
        aptr[j] = g_seq   + (size_t)am * IND + lcol[j];
        bptr[j] = g_wih32 + (size_t)(bn + lrow[j]) * IND + lcol[j];
    }

    float c[4][4][4];
    #pragma unroll
    for (int mi = 0; mi < 4; mi++)
        #pragma unroll
        for (int ni = 0; ni < 4; ni++)
            #pragma unroll
            for (int r = 0; r < 4; r++) c[mi][ni][r] = 0.f;

    // prologue: stage 0
    #pragma unroll
    for (int j = 0; j < 4; j++) {
        unsigned int off = (unsigned int)(lrow[j] * TLEN + lcol[j]) * 4u;
        cp16(sA + off, aptr[j]);
        cp16(sB + off, bptr[j]);
    }
    asm volatile("cp.async.commit_group;" ::: "memory");

    const int NIT = IND / 32;   // 192
    for (int it = 0; it < NIT; it++) {
        const int s = it & 1;
        if (it + 1 < NIT) {
            const int koff = (it + 1) * 32;
            const unsigned int sbase = (unsigned int)((1 - s) * TBUF) * 4u;
            #pragma unroll
            for (int j = 0; j < 4; j++) {
                unsigned int off = sbase + (unsigned int)(lrow[j] * TLEN + lcol[j]) * 4u;
                cp16(sA + off, aptr[j] + koff);
                cp16(sB + off, bptr[j] + koff);
            }
            asm volatile("cp.async.commit_group;" ::: "memory");
            asm volatile("cp.async.wait_group 1;" ::: "memory");
        } else {
            asm volatile("cp.async.wait_group 0;" ::: "memory");
        }
        __syncthreads();

        const float* Ax = As + s * TBUF;
        const float* Bx = Bs + s * TBUF;
        #pragma unroll
        for (int ks = 0; ks < 4; ks++) {
            const int kk = ks * 8;
            unsigned int af[4][4], bf[4][2];
            #pragma unroll
            for (int mi = 0; mi < 4; mi++) {
                const float* p = Ax + (wm + mi * 16 + gid) * TLEN + kk + tig;
                af[mi][0] = __float_as_uint(p[0]);
                af[mi][1] = __float_as_uint(p[8 * TLEN]);
                af[mi][2] = __float_as_uint(p[4]);
                af[mi][3] = __float_as_uint(p[8 * TLEN + 4]);
            }
            #pragma unroll
            for (int ni = 0; ni < 4; ni++) {
                const float* p = Bx + (wn + ni * 8 + gid) * TLEN + kk + tig;
                bf[ni][0] = __float_as_uint(p[0]);
                bf[ni][1] = __float_as_uint(p[4]);
            }
            #pragma unroll
            for (int mi = 0; mi < 4; mi++)
                #pragma unroll
                for (int ni = 0; ni < 4; ni++) {
                    asm volatile(
                        "mma.sync.aligned.m16n8k8.row.col.f32.tf32.tf32.f32 "
                        "{%0,%1,%2,%3}, {%4,%5,%6,%7}, {%8,%9}, {%0,%1,%2,%3};\n"
                        : "+f"(c[mi][ni][0]), "+f"(c[mi][ni][1]),
                          "+f"(c[mi][ni][2]), "+f"(c[mi][ni][3])
                        : "r"(af[mi][0]), "r"(af[mi][1]), "r"(af[mi][2]), "r"(af[mi][3]),
                          "r"(bf[ni][0]), "r"(bf[ni][1]));
                }
        }
        __syncthreads();
    }

    // epilogue: +bih, guarded stores (float2)
    #pragma unroll
    for (int ni = 0; ni < 4; ni++) {
        const int n0 = bn + wn + ni * 8 + tig * 2;
        const float bb0 = bih[n0], bb1 = bih[n0 + 1];
        #pragma unroll
        for (int mi = 0; mi < 4; mi++) {
            const int m0 = bm + wm + mi * 16 + gid;
            if (m0 < BB * TT) {
                float2 v = make_float2(c[mi][ni][0] + bb0, c[mi][ni][1] + bb1);
                *(float2*)(g_gx + (size_t)m0 * G3 + n0) = v;
            }
            if (m0 + 8 < BB * TT) {
                float2 v = make_float2(c[mi][ni][2] + bb0, c[mi][ni][3] + bb1);
                *(float2*)(g_gx + (size_t)(m0 + 8) * G3 + n0) = v;
            }
        }
    }
}

// =====================================================================
// software grid barrier: two-level (8 group counters -> master -> epoch)
// =====================================================================
__device__ __forceinline__ void grid_barrier(int e, int bid) {
    __syncthreads();
    if (threadIdx.x == 0) {
        __threadfence();
        int g = (bid & 7) * 32;
        int v = atomicAdd(&g_cnt[g], 1);
        if (v == (GRU_BLOCKS / 8) - 1) {
            atomicExch(&g_cnt[g], 0);
            int m = atomicAdd(&g_master, 1);
            if (m == 7) {
                atomicExch(&g_master, 0);
                __threadfence();
                g_epoch = e;
            }
        }
        while (g_epoch < e) { }
        __threadfence();
    }
    __syncthreads();
}

// =====================================================================
// persistent GRU: ONE kernel for all 1000 timesteps.
// 128 blocks x 384 threads; warp per j (12 j's/block), all 4 batches/warp.
// =====================================================================
__global__ __launch_bounds__(GRU_THREADS, 1) void k_gru_persist(
    const float* __restrict__ Whh, const float* __restrict__ bhh,
    const float* __restrict__ gx, float* __restrict__ out)
{
    __shared__ __align__(16) float hs[BB * HID];

    const int tid = threadIdx.x;
    const int lane = tid & 31, warp = tid >> 5;
    const int bid = blockIdx.x;
    const int j = bid * 12 + warp;

    const float4* wr = (const float4*)(Whh + (size_t)j * HID);
    const float4* wz = (const float4*)(Whh + (size_t)(HID + j) * HID);
    const float4* wn = (const float4*)(Whh + (size_t)(2 * HID + j) * HID);
    const float bhr = bhh[j], bhz = bhh[HID + j], bhn = bhh[2 * HID + j];
    const int c = j / FF, f = j - c * FF;

    for (int t = 0; t < TT; t++) {
        const float4* hp4 = (const float4*)g_h[t & 1];
        float4* hs4 = (float4*)hs;
        #pragma unroll
        for (int i = 0; i < 4; i++) hs4[tid + i * GRU_THREADS] = hp4[tid + i * GRU_THREADS];
        __syncthreads();

        float ar[4] = {0.f,0.f,0.f,0.f};
        float az[4] = {0.f,0.f,0.f,0.f};
        float an[4] = {0.f,0.f,0.f,0.f};

        #pragma unroll 4
        for (int k = lane; k < HID / 4; k += 32) {
            float4 r4 = wr[k], z4 = wz[k], n4 = wn[k];
            #pragma unroll
            for (int b = 0; b < 4; b++) {
                float4 h4 = hs4[b * (HID / 4) + k];
                ar[b] += r4.x * h4.x + r4.y * h4.y + r4.z * h4.z + r4.w * h4.w;
                az[b] += z4.x * h4.x + z4.y * h4.y + z4.z * h4.z + z4.w * h4.w;
                an[b] += n4.x * h4.x + n4.y * h4.y + n4.z * h4.z + n4.w * h4.w;
            }
        }
        #pragma unroll
        for (int off = 16; off; off >>= 1) {
            #pragma unroll
            for (int b = 0; b < 4; b++) {
                ar[b] += __shfl_xor_sync(0xffffffffu, ar[b], off);
                az[b] += __shfl_xor_sync(0xffffffffu, az[b], off);
                an[b] += __shfl_xor_sync(0xffffffffu, an[b], off);
            }
        }

        if (lane < 4) {
            const int b = lane;
            float sr, sz, sn;
            if      (b == 0) { sr = ar[0]; sz = az[0]; sn = an[0]; }
            else if (b == 1) { sr = ar[1]; sz = az[1]; sn = an[1]; }
            else if (b == 2) { sr = ar[2]; sz = az[2]; sn = an[2]; }
            else             { sr = ar[3]; sz = az[3]; sn = an[3]; }

            float ghr = sr + bhr;
            float ghz = sz + bhz;
            float ghn = sn + bhn;

            size_t gxb = ((size_t)b * TT + t) * G3;
            float r = 1.f / (1.f + expf(-(gx[gxb + j]           + ghr)));
            float z = 1.f / (1.f + expf(-(gx[gxb + HID + j]     + ghz)));
            float n = tanhf(      gx[gxb + 2 * HID + j] + r * ghn);
            float hp = hs[b * HID + j];
            float hn = (1.f - z) * n + z * hp;

            g_h[(t + 1) & 1][b * HID + j] = hn;
            out[(((size_t)b * CC + c) * TT + t) * FF + f] = hn;
            if (t == TT - 1) out[(size_t)BB * CC * TT * FF + b * HID + j] = hn;
        }

        grid_barrier(t + 1, bid);
    }
}

// =====================================================================
extern "C" void kernel_launch(void* const* d_in, const int* in_sizes, int n_in,
                              void* d_out, int out_size)
{
    const float* x   = (const float*)d_in[0];
    const float* h0  = (const float*)d_in[1];
    const float* Wq  = (const float*)d_in[2];
    const float* bq  = (const float*)d_in[3];
    const float* Wk  = (const float*)d_in[4];
    const float* bk  = (const float*)d_in[5];
    const float* Wv  = (const float*)d_in[6];
    const float* bv  = (const float*)d_in[7];
    const float* Wih = (const float*)d_in[8];
    const float* Whh = (const float*)d_in[9];
    const float* bih = (const float*)d_in[10];
    const float* bhh = (const float*)d_in[11];
    float* out = (float*)d_out;

    const int smem_attn = 38816 * (int)sizeof(float);    // ~152 KB
    const int smem_gemm = 4 * TBUF * (int)sizeof(float); // 73728 B
    cudaFuncSetAttribute(k_attn,     cudaFuncAttributeMaxDynamicSharedMemorySize, smem_attn);
    cudaFuncSetAttribute(k_gemm_t32, cudaFuncAttributeMaxDynamicSharedMemorySize, smem_gemm);

    float* gxp = nullptr;
    cudaGetSymbolAddress((void**)&gxp, g_gx);

    k_init<<<(BB * HID + 255) / 256, 256>>>(h0);
    k_cvt<<<1024, 256>>>(Wih);
    k_attn<<<dim3(TT, BB), 256, smem_attn>>>(x, Wq, bq, Wk, bk, Wv, bv);
    k_gemm_t32<<<dim3(G3 / 128, (BB * TT + 127) / 128), 256, smem_gemm>>>(bih);
    k_gru_persist<<<GRU_BLOCKS, GRU_THREADS>>>(Whh, bhh, gxp, out);
}

// round 13
// speedup vs baseline: 1.4217x; 1.0602x over previous
#include <cuda_runtime.h>
#include <cuda_bf16.h>
#include <stdint.h>
#include <math.h>

#define BB   4
#define CC   16
#define TT   1000
#define FF   96
#define HH   64
#define HID  1536
#define IND  6144
#define G3   4608

#define GRU_BLOCKS 128
#define GRU_THREADS 384

// ---- scratch (device globals: no allocation allowed) ----
__device__ __align__(16) __nv_bfloat16 g_seq16[(size_t)BB * TT * IND];  // attn out, bf16
__device__ __align__(16) __nv_bfloat16 g_wih16[(size_t)G3 * IND];       // Wih, bf16
__device__ __align__(16) float g_gx [(size_t)BB * TT * G3];             // GEMM out fp32
__device__ __align__(16) float g_h  [2][BB * HID];                      // GRU state

// ---- software grid barrier state ----
__device__ int          g_cnt[8 * 32];
__device__ int          g_master;
__device__ volatile int g_epoch;

// =====================================================================
__global__ void k_init(const float* __restrict__ h0) {
    int i = blockIdx.x * blockDim.x + threadIdx.x;
    if (i < BB * HID) g_h[0][i] = h0[i];
    if (i < 8 * 32) g_cnt[i] = 0;
    if (i == 0) { g_master = 0; g_epoch = 0; }
}

// =====================================================================
// Wih -> bf16 (one-time per replay, streaming)
// =====================================================================
__global__ void k_cvt(const float* __restrict__ Wih) {
    const size_t n = (size_t)G3 * IND;
    for (size_t i = ((size_t)blockIdx.x * blockDim.x + threadIdx.x) * 4; i < n;
         i += (size_t)gridDim.x * blockDim.x * 4) {
        float4 v = *(const float4*)(Wih + i);
        __nv_bfloat162 a; a.x = __float2bfloat16(v.x); a.y = __float2bfloat16(v.y);
        __nv_bfloat162 b; b.x = __float2bfloat16(v.z); b.y = __float2bfloat16(v.w);
        *(__nv_bfloat162*)(g_wih16 + i)     = a;
        *(__nv_bfloat162*)(g_wih16 + i + 2) = b;
    }
}

// =====================================================================
// fused conv(1x3) q/k/v + per-(b,t) joint-2D-softmax attention
// epilogue emits bf16 (feeds bf16 tensor GEMM only)
// =====================================================================
__global__ __launch_bounds__(256) void k_attn(
    const float* __restrict__ x,
    const float* __restrict__ Wq, const float* __restrict__ bq,
    const float* __restrict__ Wk, const float* __restrict__ bk,
    const float* __restrict__ Wv, const float* __restrict__ bv)
{
    extern __shared__ float sm[];
    float* xs  = sm;
    float* wq  = xs  + 16 * 98;
    float* wk  = wq  + 3072;
    float* wv  = wk  + 3072;
    float* bqs = wv  + 3072;
    float* bks = bqs + 64;
    float* bvs = bks + 64;
    float* qs  = bvs + 64;
    float* ks  = qs  + 64 * 97;
    float* vs  = ks  + 64 * 97;
    float* ss  = vs  + 64 * 97;
    __shared__ float red[16];

    const int tid = threadIdx.x;
    const int t = blockIdx.x, b = blockIdx.y;

    for (int i = tid; i < 3072; i += 256) { wq[i] = Wq[i]; wk[i] = Wk[i]; wv[i] = Wv[i]; }
    if (tid < 64) { bqs[tid] = bq[tid]; bks[tid] = bk[tid]; bvs[tid] = bv[tid]; }

    for (int i = tid; i < CC * FF; i += 256) {
        int c = i / FF, f = i - c * FF;
        xs[c * 98 + f + 1] = x[(((size_t)b * CC + c) * TT + t) * FF + f];
    }
    if (tid < 2 * CC) { int c = tid >> 1; xs[c * 98 + ((tid & 1) ? 97 : 0)] = 0.f; }
    __syncthreads();

    for (int e = tid; e < HH * FF; e += 256) {
        int h = e / FF, f = e - h * FF;
        float aq = bqs[h], ak = bks[h], av = bvs[h];
        const float* wqr = wq + h * 48;
        const float* wkr = wk + h * 48;
        const float* wvr = wv + h * 48;
        #pragma unroll 4
        for (int c = 0; c < CC; c++) {
            float x0 = xs[c * 98 + f], x1 = xs[c * 98 + f + 1], x2 = xs[c * 98 + f + 2];
            aq += x0 * wqr[c * 3] + x1 * wqr[c * 3 + 1] + x2 * wqr[c * 3 + 2];
            ak += x0 * wkr[c * 3] + x1 * wkr[c * 3 + 1] + x2 * wkr[c * 3 + 2];
            av += x0 * wvr[c * 3] + x1 * wvr[c * 3 + 1] + x2 * wvr[c * 3 + 2];
        }
        qs[h * 97 + f] = aq; ks[h * 97 + f] = ak; vs[h * 97 + f] = av;
    }
    __syncthreads();

    for (int e = tid; e < 2304; e += 256) {
        int f0 = e / 48, g0 = e - f0 * 48;
        float a00 = 0.f, a01 = 0.f, a10 = 0.f, a11 = 0.f;
        #pragma unroll 4
        for (int h = 0; h < HH; h++) {
            float q0 = qs[h * 97 + f0], q1 = qs[h * 97 + f0 + 48];
            float k0 = ks[h * 97 + g0], k1 = ks[h * 97 + g0 + 48];
            a00 += q0 * k0; a01 += q0 * k1; a10 += q1 * k0; a11 += q1 * k1;
        }
        ss[f0 * 96 + g0]             = a00 * 0.125f;
        ss[f0 * 96 + g0 + 48]        = a01 * 0.125f;
        ss[(f0 + 48) * 96 + g0]      = a10 * 0.125f;
        ss[(f0 + 48) * 96 + g0 + 48] = a11 * 0.125f;
    }
    __syncthreads();

    float m = -1e30f;
    for (int e = tid; e < 9216; e += 256) m = fmaxf(m, ss[e]);
    #pragma unroll
    for (int off = 16; off; off >>= 1) m = fmaxf(m, __shfl_xor_sync(0xffffffffu, m, off));
    if ((tid & 31) == 0) red[tid >> 5] = m;
    __syncthreads();
    if (tid == 0) { float mm = red[0]; for (int i = 1; i < 8; i++) mm = fmaxf(mm, red[i]); red[0] = mm; }
    __syncthreads();
    const float M = red[0];

    float s = 0.f;
    for (int e = tid; e < 9216; e += 256) { float v = expf(ss[e] - M); ss[e] = v; s += v; }
    #pragma unroll
    for (int off = 16; off; off >>= 1) s += __shfl_xor_sync(0xffffffffu, s, off);
    if ((tid & 31) == 0) red[8 + (tid >> 5)] = s;
    __syncthreads();
    if (tid == 0) { float tt = 0.f; for (int i = 0; i < 8; i++) tt += red[8 + i]; red[8] = 1.0f / tt; }
    __syncthreads();
    const float inv = red[8];

    __nv_bfloat16* seqp = g_seq16 + (size_t)(b * TT + t) * IND;
    for (int e = tid; e < 1536; e += 256) {
        int f0 = e >> 5, h0 = e & 31;
        float a00 = 0.f, a01 = 0.f, a10 = 0.f, a11 = 0.f;
        #pragma unroll 4
        for (int g = 0; g < 96; g++) {
            float s0 = ss[f0 * 96 + g], s1 = ss[(f0 + 48) * 96 + g];
            float v0 = vs[h0 * 97 + g], v1 = vs[(h0 + 32) * 97 + g];
            a00 += s0 * v0; a01 += s0 * v1; a10 += s1 * v0; a11 += s1 * v1;
        }
        seqp[f0 * 64 + h0]             = __float2bfloat16(a00 * inv);
        seqp[f0 * 64 + h0 + 32]        = __float2bfloat16(a01 * inv);
        seqp[(f0 + 48) * 64 + h0]      = __float2bfloat16(a10 * inv);
        seqp[(f0 + 48) * 64 + h0 + 32] = __float2bfloat16(a11 * inv);
    }
}

// =====================================================================
// bf16 mma.sync GEMM: gx = seq @ Wih^T + bih
// [4000,6144] x [4608,6144]^T -> [4000,4608]
// 128x128x32 tiles, 8 warps (2x4), warp tile 64x32, mma.m16n8k16.bf16,
// ldmatrix.x4 fragment loads, 3-stage cp.async pipeline.
// smem row stride 80B -> conflict-free ldmatrix phases + 16B alignment.
// =====================================================================
#define BK      32                     // bf16 k per tile
#define RSTRIDE 80                     // bytes per 128-row tile row (64 data + 16 pad)
#define STAGE_B (128 * RSTRIDE)        // 10240 B per matrix per stage
#define STG     (2 * STAGE_B)          // 20480 B per stage (A+B)
#define GEMM_SMEM (3 * STG)            // 61440 B

#define LDSM4(r0, r1, r2, r3, a) \
    asm volatile("ldmatrix.sync.aligned.m8n8.x4.shared.b16 {%0,%1,%2,%3}, [%4];" \
                 : "=r"(r0), "=r"(r1), "=r"(r2), "=r"(r3) : "r"(a))

__global__ __launch_bounds__(256) void k_gemm_bf(const float* __restrict__ bih)
{
    extern __shared__ __align__(16) char smem[];
    const unsigned sbase = (unsigned)__cvta_generic_to_shared(smem);

    const int tid  = threadIdx.x;
    const int bm   = blockIdx.y * 128;
    const int bn   = blockIdx.x * 128;
    const int w    = tid >> 5;
    const int lane = tid & 31;
    const int wm   = (w & 1) * 64;
    const int wn   = (w >> 1) * 32;
    const int gid  = lane >> 2;
    const int tig  = lane & 3;

    // ---- cp.async coords: 1024 16B-chunks/stage, 4 per thread ----
    const __nv_bfloat16* gptr[4];
    unsigned soff[4];
    #pragma unroll
    for (int j = 0; j < 4; j++) {
        int q = tid + j * 256;               // 0..1023
        int isB = (q >= 512);
        int qq = q & 511;
        int r = qq >> 2, ch = qq & 3;        // row 0..127, chunk 0..3
        if (!isB) {
            int m = bm + r; if (m > BB * TT - 1) m = BB * TT - 1;   // clamp; stores guarded
            gptr[j] = g_seq16 + (size_t)m * IND + ch * 8;
        } else {
            gptr[j] = g_wih16 + (size_t)(bn + r) * IND + ch * 8;
        }
        soff[j] = (unsigned)(isB * STAGE_B + r * RSTRIDE + ch * 16);
    }

    float c[4][4][4];
    #pragma unroll
    for (int mi = 0; mi < 4; mi++)
        #pragma unroll
        for (int ni = 0; ni < 4; ni++)
            #pragma unroll
            for (int r = 0; r < 4; r++) c[mi][ni][r] = 0.f;

    auto load_stage = [&](int s, int k0) {
        const unsigned st = sbase + (unsigned)(s * STG);
        #pragma unroll
        for (int j = 0; j < 4; j++)
            asm volatile("cp.async.cg.shared.global [%0], [%1], 16;"
                         :: "r"(st + soff[j]), "l"(gptr[j] + k0) : "memory");
        asm volatile("cp.async.commit_group;" ::: "memory");
    };

    load_stage(0, 0);
    load_stage(1, BK);

    // ldmatrix base offsets (row = lane&15, k-half = lane>>4)
    const unsigned lrow = (unsigned)(lane & 15);
    const unsigned lkh  = (unsigned)((lane >> 4) * 16);

    const int NIT = IND / BK;   // 192
    for (int it = 0; it < NIT; it++) {
        if (it + 1 < NIT) asm volatile("cp.async.wait_group 1;" ::: "memory");
        else              asm volatile("cp.async.wait_group 0;" ::: "memory");
        __syncthreads();
        if (it + 2 < NIT) load_stage((it + 2) % 3, (it + 2) * BK);

        const unsigned aS = sbase + (unsigned)((it % 3) * STG);
        const unsigned bS = aS + STAGE_B;

        #pragma unroll
        for (int ks = 0; ks < 2; ks++) {
            const unsigned kb = (unsigned)(ks * 32) + lkh;
            unsigned af[4][4], bf[4][2];
            #pragma unroll
            for (int mi = 0; mi < 4; mi++) {
                unsigned a = aS + (unsigned)(wm + mi * 16 + lrow) * RSTRIDE + kb;
                LDSM4(af[mi][0], af[mi][1], af[mi][2], af[mi][3], a);
            }
            #pragma unroll
            for (int np = 0; np < 2; np++) {
                unsigned a = bS + (unsigned)(wn + np * 16 + lrow) * RSTRIDE + kb;
                unsigned r0, r1, r2, r3;
                LDSM4(r0, r1, r2, r3, a);
                bf[2 * np][0] = r0; bf[2 * np + 1][0] = r1;
                bf[2 * np][1] = r2; bf[2 * np + 1][1] = r3;
            }
            #pragma unroll
            for (int mi = 0; mi < 4; mi++)
                #pragma unroll
                for (int ni = 0; ni < 4; ni++) {
                    asm volatile(
                        "mma.sync.aligned.m16n8k16.row.col.f32.bf16.bf16.f32 "
                        "{%0,%1,%2,%3}, {%4,%5,%6,%7}, {%8,%9}, {%0,%1,%2,%3};\n"
                        : "+f"(c[mi][ni][0]), "+f"(c[mi][ni][1]),
                          "+f"(c[mi][ni][2]), "+f"(c[mi][ni][3])
                        : "r"(af[mi][0]), "r"(af[mi][1]), "r"(af[mi][2]), "r"(af[mi][3]),
                          "r"(bf[ni][0]), "r"(bf[ni][1]));
                }
        }
    }

    // epilogue: +bih, guarded float2 stores
    #pragma unroll
    for (int ni = 0; ni < 4; ni++) {
        const int n0 = bn + wn + ni * 8 + tig * 2;
        const float bb0 = bih[n0], bb1 = bih[n0 + 1];
        #pragma unroll
        for (int mi = 0; mi < 4; mi++) {
            const int m0 = bm + wm + mi * 16 + gid;
            if (m0 < BB * TT) {
                float2 v = make_float2(c[mi][ni][0] + bb0, c[mi][ni][1] + bb1);
                *(float2*)(g_gx + (size_t)m0 * G3 + n0) = v;
            }
            if (m0 + 8 < BB * TT) {
                float2 v = make_float2(c[mi][ni][2] + bb0, c[mi][ni][3] + bb1);
                *(float2*)(g_gx + (size_t)(m0 + 8) * G3 + n0) = v;
            }
        }
    }
}

// =====================================================================
// software grid barrier: two-level (8 group counters -> master -> epoch)
// =====================================================================
__device__ __forceinline__ void grid_barrier(int e, int bid) {
    __syncthreads();
    if (threadIdx.x == 0) {
        __threadfence();
        int g = (bid & 7) * 32;
        int v = atomicAdd(&g_cnt[g], 1);
        if (v == (GRU_BLOCKS / 8) - 1) {
            atomicExch(&g_cnt[g], 0);
            int m = atomicAdd(&g_master, 1);
            if (m == 7) {
                atomicExch(&g_master, 0);
                __threadfence();
                g_epoch = e;
            }
        }
        while (g_epoch < e) { }
        __threadfence();
    }
    __syncthreads();
}

// =====================================================================
// persistent GRU: ONE kernel for all 1000 timesteps (validated R9/R11)
// =====================================================================
__global__ __launch_bounds__(GRU_THREADS, 1) void k_gru_persist(
    const float* __restrict__ Whh, const float* __restrict__ bhh,
    const float* __restrict__ gx, float* __restrict__ out)
{
    __shared__ __align__(16) float hs[BB * HID];

    const int tid = threadIdx.x;
    const int lane = tid & 31, warp = tid >> 5;
    const int bid = blockIdx.x;
    const int j = bid * 12 + warp;

    const float4* wr = (const float4*)(Whh + (size_t)j * HID);
    const float4* wz = (const float4*)(Whh + (size_t)(HID + j) * HID);
    const float4* wn = (const float4*)(Whh + (size_t)(2 * HID + j) * HID);
    const float bhr = bhh[j], bhz = bhh[HID + j], bhn = bhh[2 * HID + j];
    const int c = j / FF, f = j - c * FF;

    for (int t = 0; t < TT; t++) {
        const float4* hp4 = (const float4*)g_h[t & 1];
        float4* hs4 = (float4*)hs;
        #pragma unroll
        for (int i = 0; i < 4; i++) hs4[tid + i * GRU_THREADS] = hp4[tid + i * GRU_THREADS];
        __syncthreads();

        float ar[4] = {0.f,0.f,0.f,0.f};
        float az[4] = {0.f,0.f,0.f,0.f};
        float an[4] = {0.f,0.f,0.f,0.f};

        #pragma unroll 4
        for (int k = lane; k < HID / 4; k += 32) {
            float4 r4 = wr[k], z4 = wz[k], n4 = wn[k];
            #pragma unroll
            for (int b = 0; b < 4; b++) {
                float4 h4 = hs4[b * (HID / 4) + k];
                ar[b] += r4.x * h4.x + r4.y * h4.y + r4.z * h4.z + r4.w * h4.w;
                az[b] += z4.x * h4.x + z4.y * h4.y + z4.z * h4.z + z4.w * h4.w;
                an[b] += n4.x * h4.x + n4.y * h4.y + n4.z * h4.z + n4.w * h4.w;
            }
        }
        #pragma unroll
        for (int off = 16; off; off >>= 1) {
            #pragma unroll
            for (int b = 0; b < 4; b++) {
                ar[b] += __shfl_xor_sync(0xffffffffu, ar[b], off);
                az[b] += __shfl_xor_sync(0xffffffffu, az[b], off);
                an[b] += __shfl_xor_sync(0xffffffffu, an[b], off);
            }
        }

        if (lane < 4) {
            const int b = lane;
            float sr, sz, sn;
            if      (b == 0) { sr = ar[0]; sz = az[0]; sn = an[0]; }
            else if (b == 1) { sr = ar[1]; sz = az[1]; sn = an[1]; }
            else if (b == 2) { sr = ar[2]; sz = az[2]; sn = an[2]; }
            else             { sr = ar[3]; sz = az[3]; sn = an[3]; }

            float ghr = sr + bhr;
            float ghz = sz + bhz;
            float ghn = sn + bhn;

            size_t gxb = ((size_t)b * TT + t) * G3;
            float r = 1.f / (1.f + expf(-(gx[gxb + j]           + ghr)));
            float z = 1.f / (1.f + expf(-(gx[gxb + HID + j]     + ghz)));
            float n = tanhf(      gx[gxb + 2 * HID + j] + r * ghn);
            float hp = hs[b * HID + j];
            float hn = (1.f - z) * n + z * hp;

            g_h[(t + 1) & 1][b * HID + j] = hn;
            out[(((size_t)b * CC + c) * TT + t) * FF + f] = hn;
            if (t == TT - 1) out[(size_t)BB * CC * TT * FF + b * HID + j] = hn;
        }

        grid_barrier(t + 1, bid);
    }
}

// =====================================================================
extern "C" void kernel_launch(void* const* d_in, const int* in_sizes, int n_in,
                              void* d_out, int out_size)
{
    const float* x   = (const float*)d_in[0];
    const float* h0  = (const float*)d_in[1];
    const float* Wq  = (const float*)d_in[2];
    const float* bq  = (const float*)d_in[3];
    const float* Wk  = (const float*)d_in[4];
    const float* bk  = (const float*)d_in[5];
    const float* Wv  = (const float*)d_in[6];
    const float* bv  = (const float*)d_in[7];
    const float* Wih = (const float*)d_in[8];
    const float* Whh = (const float*)d_in[9];
    const float* bih = (const float*)d_in[10];
    const float* bhh = (const float*)d_in[11];
    float* out = (float*)d_out;

    const int smem_attn = 38816 * (int)sizeof(float);   // ~152 KB
    cudaFuncSetAttribute(k_attn,    cudaFuncAttributeMaxDynamicSharedMemorySize, smem_attn);
    cudaFuncSetAttribute(k_gemm_bf, cudaFuncAttributeMaxDynamicSharedMemorySize, GEMM_SMEM);

    float* gxp = nullptr;
    cudaGetSymbolAddress((void**)&gxp, g_gx);

    k_init<<<(BB * HID + 255) / 256, 256>>>(h0);
    k_cvt<<<1024, 256>>>(Wih);
    k_attn<<<dim3(TT, BB), 256, smem_attn>>>(x, Wq, bq, Wk, bk, Wv, bv);
    k_gemm_bf<<<dim3(G3 / 128, (BB * TT + 127) / 128), 256, GEMM_SMEM>>>(bih);
    k_gru_persist<<<GRU_BLOCKS, GRU_THREADS>>>(Whh, bhh, gxp, out);
}

// round 17
// speedup vs baseline: 1.5106x; 1.0625x over previous
#include <cuda_runtime.h>
#include <cuda_bf16.h>
#include <cuda_fp16.h>
#include <stdint.h>
#include <math.h>

#define BB   4
#define CC   16
#define TT   1000
#define FF   96
#define HH   64
#define HID  1536
#define IND  6144
#define G3   4608

#define GRU_BLOCKS 128
#define GRU_THREADS 384

// ---- scratch (device globals: no allocation allowed) ----
__device__ __align__(16) __nv_bfloat16 g_seq16[(size_t)BB * TT * IND];  // attn out, bf16
__device__ __align__(16) __nv_bfloat16 g_wih16[(size_t)G3 * IND];       // Wih, bf16
__device__ __align__(16) float g_gx [(size_t)BB * TT * G3];             // GEMM out fp32
__device__ __align__(16) float g_h  [2][BB * HID];                      // GRU state

// ---- software grid barrier state ----
__device__ int          g_cnt[8 * 32];
__device__ int          g_master;
__device__ volatile int g_epoch;

// =====================================================================
__global__ void k_init(const float* __restrict__ h0) {
    int i = blockIdx.x * blockDim.x + threadIdx.x;
    if (i < BB * HID) g_h[0][i] = h0[i];
    if (i < 8 * 32) g_cnt[i] = 0;
    if (i == 0) { g_master = 0; g_epoch = 0; }
}

// =====================================================================
// Wih -> bf16 (one-time per replay, streaming)
// =====================================================================
__global__ void k_cvt(const float* __restrict__ Wih) {
    const size_t n = (size_t)G3 * IND;
    for (size_t i = ((size_t)blockIdx.x * blockDim.x + threadIdx.x) * 4; i < n;
         i += (size_t)gridDim.x * blockDim.x * 4) {
        float4 v = *(const float4*)(Wih + i);
        __nv_bfloat162 a; a.x = __float2bfloat16(v.x); a.y = __float2bfloat16(v.y);
        __nv_bfloat162 b; b.x = __float2bfloat16(v.z); b.y = __float2bfloat16(v.w);
        *(__nv_bfloat162*)(g_wih16 + i)     = a;
        *(__nv_bfloat162*)(g_wih16 + i + 2) = b;
    }
}

// =====================================================================
// fused conv(1x3) q/k/v + per-(b,t) joint-2D-softmax attention
// (validated; epilogue emits bf16 for the tensor GEMM)
// =====================================================================
__global__ __launch_bounds__(256) void k_attn(
    const float* __restrict__ x,
    const float* __restrict__ Wq, const float* __restrict__ bq,
    const float* __restrict__ Wk, const float* __restrict__ bk,
    const float* __restrict__ Wv, const float* __restrict__ bv)
{
    extern __shared__ float sm[];
    float* xs  = sm;
    float* wq  = xs  + 16 * 98;
    float* wk  = wq  + 3072;
    float* wv  = wk  + 3072;
    float* bqs = wv  + 3072;
    float* bks = bqs + 64;
    float* bvs = bks + 64;
    float* qs  = bvs + 64;
    float* ks  = qs  + 64 * 97;
    float* vs  = ks  + 64 * 97;
    float* ss  = vs  + 64 * 97;
    __shared__ float red[16];

    const int tid = threadIdx.x;
    const int t = blockIdx.x, b = blockIdx.y;

    for (int i = tid; i < 3072; i += 256) { wq[i] = Wq[i]; wk[i] = Wk[i]; wv[i] = Wv[i]; }
    if (tid < 64) { bqs[tid] = bq[tid]; bks[tid] = bk[tid]; bvs[tid] = bv[tid]; }

    for (int i = tid; i < CC * FF; i += 256) {
        int c = i / FF, f = i - c * FF;
        xs[c * 98 + f + 1] = x[(((size_t)b * CC + c) * TT + t) * FF + f];
    }
    if (tid < 2 * CC) { int c = tid >> 1; xs[c * 98 + ((tid & 1) ? 97 : 0)] = 0.f; }
    __syncthreads();

    for (int e = tid; e < HH * FF; e += 256) {
        int h = e / FF, f = e - h * FF;
        float aq = bqs[h], ak = bks[h], av = bvs[h];
        const float* wqr = wq + h * 48;
        const float* wkr = wk + h * 48;
        const float* wvr = wv + h * 48;
        #pragma unroll 4
        for (int c = 0; c < CC; c++) {
            float x0 = xs[c * 98 + f], x1 = xs[c * 98 + f + 1], x2 = xs[c * 98 + f + 2];
            aq += x0 * wqr[c * 3] + x1 * wqr[c * 3 + 1] + x2 * wqr[c * 3 + 2];
            ak += x0 * wkr[c * 3] + x1 * wkr[c * 3 + 1] + x2 * wkr[c * 3 + 2];
            av += x0 * wvr[c * 3] + x1 * wvr[c * 3 + 1] + x2 * wvr[c * 3 + 2];
        }
        qs[h * 97 + f] = aq; ks[h * 97 + f] = ak; vs[h * 97 + f] = av;
    }
    __syncthreads();

    for (int e = tid; e < 2304; e += 256) {
        int f0 = e / 48, g0 = e - f0 * 48;
        float a00 = 0.f, a01 = 0.f, a10 = 0.f, a11 = 0.f;
        #pragma unroll 4
        for (int h = 0; h < HH; h++) {
            float q0 = qs[h * 97 + f0], q1 = qs[h * 97 + f0 + 48];
            float k0 = ks[h * 97 + g0], k1 = ks[h * 97 + g0 + 48];
            a00 += q0 * k0; a01 += q0 * k1; a10 += q1 * k0; a11 += q1 * k1;
        }
        ss[f0 * 96 + g0]             = a00 * 0.125f;
        ss[f0 * 96 + g0 + 48]        = a01 * 0.125f;
        ss[(f0 + 48) * 96 + g0]      = a10 * 0.125f;
        ss[(f0 + 48) * 96 + g0 + 48] = a11 * 0.125f;
    }
    __syncthreads();

    float m = -1e30f;
    for (int e = tid; e < 9216; e += 256) m = fmaxf(m, ss[e]);
    #pragma unroll
    for (int off = 16; off; off >>= 1) m = fmaxf(m, __shfl_xor_sync(0xffffffffu, m, off));
    if ((tid & 31) == 0) red[tid >> 5] = m;
    __syncthreads();
    if (tid == 0) { float mm = red[0]; for (int i = 1; i < 8; i++) mm = fmaxf(mm, red[i]); red[0] = mm; }
    __syncthreads();
    const float M = red[0];

    float s = 0.f;
    for (int e = tid; e < 9216; e += 256) { float v = expf(ss[e] - M); ss[e] = v; s += v; }
    #pragma unroll
    for (int off = 16; off; off >>= 1) s += __shfl_xor_sync(0xffffffffu, s, off);
    if ((tid & 31) == 0) red[8 + (tid >> 5)] = s;
    __syncthreads();
    if (tid == 0) { float tt = 0.f; for (int i = 0; i < 8; i++) tt += red[8 + i]; red[8] = 1.0f / tt; }
    __syncthreads();
    const float inv = red[8];

    __nv_bfloat16* seqp = g_seq16 + (size_t)(b * TT + t) * IND;
    for (int e = tid; e < 1536; e += 256) {
        int f0 = e >> 5, h0 = e & 31;
        float a00 = 0.f, a01 = 0.f, a10 = 0.f, a11 = 0.f;
        #pragma unroll 4
        for (int g = 0; g < 96; g++) {
            float s0 = ss[f0 * 96 + g], s1 = ss[(f0 + 48) * 96 + g];
            float v0 = vs[h0 * 97 + g], v1 = vs[(h0 + 32) * 97 + g];
            a00 += s0 * v0; a01 += s0 * v1; a10 += s1 * v0; a11 += s1 * v1;
        }
        seqp[f0 * 64 + h0]             = __float2bfloat16(a00 * inv);
        seqp[f0 * 64 + h0 + 32]        = __float2bfloat16(a01 * inv);
        seqp[(f0 + 48) * 64 + h0]      = __float2bfloat16(a10 * inv);
        seqp[(f0 + 48) * 64 + h0 + 32] = __float2bfloat16(a11 * inv);
    }
}

// =====================================================================
// bf16 mma.sync GEMM (validated R13): gx = seq @ Wih^T + bih
// =====================================================================
#define BK      32
#define RSTRIDE 80
#define STAGE_B (128 * RSTRIDE)
#define STG     (2 * STAGE_B)
#define GEMM_SMEM (3 * STG)

#define LDSM4(r0, r1, r2, r3, a) \
    asm volatile("ldmatrix.sync.aligned.m8n8.x4.shared.b16 {%0,%1,%2,%3}, [%4];" \
                 : "=r"(r0), "=r"(r1), "=r"(r2), "=r"(r3) : "r"(a))

__global__ __launch_bounds__(256) void k_gemm_bf(const float* __restrict__ bih)
{
    extern __shared__ __align__(16) char smem[];
    const unsigned sbase = (unsigned)__cvta_generic_to_shared(smem);

    const int tid  = threadIdx.x;
    const int bm   = blockIdx.y * 128;
    const int bn   = blockIdx.x * 128;
    const int w    = tid >> 5;
    const int lane = tid & 31;
    const int wm   = (w & 1) * 64;
    const int wn   = (w >> 1) * 32;
    const int gid  = lane >> 2;
    const int tig  = lane & 3;

    const __nv_bfloat16* gptr[4];
    unsigned soff[4];
    #pragma unroll
    for (int j = 0; j < 4; j++) {
        int q = tid + j * 256;
        int isB = (q >= 512);
        int qq = q & 511;
        int r = qq >> 2, ch = qq & 3;
        if (!isB) {
            int m = bm + r; if (m > BB * TT - 1) m = BB * TT - 1;
            gptr[j] = g_seq16 + (size_t)m * IND + ch * 8;
        } else {
            gptr[j] = g_wih16 + (size_t)(bn + r) * IND + ch * 8;
        }
        soff[j] = (unsigned)(isB * STAGE_B + r * RSTRIDE + ch * 16);
    }

    float c[4][4][4];
    #pragma unroll
    for (int mi = 0; mi < 4; mi++)
        #pragma unroll
        for (int ni = 0; ni < 4; ni++)
            #pragma unroll
            for (int r = 0; r < 4; r++) c[mi][ni][r] = 0.f;

    auto load_stage = [&](int s, int k0) {
        const unsigned st = sbase + (unsigned)(s * STG);
        #pragma unroll
        for (int j = 0; j < 4; j++)
            asm volatile("cp.async.cg.shared.global [%0], [%1], 16;"
                         :: "r"(st + soff[j]), "l"(gptr[j] + k0) : "memory");
        asm volatile("cp.async.commit_group;" ::: "memory");
    };

    load_stage(0, 0);
    load_stage(1, BK);

    const unsigned lrow = (unsigned)(lane & 15);
    const unsigned lkh  = (unsigned)((lane >> 4) * 16);

    const int NIT = IND / BK;
    for (int it = 0; it < NIT; it++) {
        if (it + 1 < NIT) asm volatile("cp.async.wait_group 1;" ::: "memory");
        else              asm volatile("cp.async.wait_group 0;" ::: "memory");
        __syncthreads();
        if (it + 2 < NIT) load_stage((it + 2) % 3, (it + 2) * BK);

        const unsigned aS = sbase + (unsigned)((it % 3) * STG);
        const unsigned bS = aS + STAGE_B;

        #pragma unroll
        for (int ks = 0; ks < 2; ks++) {
            const unsigned kb = (unsigned)(ks * 32) + lkh;
            unsigned af[4][4], bf[4][2];
            #pragma unroll
            for (int mi = 0; mi < 4; mi++) {
                unsigned a = aS + (unsigned)(wm + mi * 16 + lrow) * RSTRIDE + kb;
                LDSM4(af[mi][0], af[mi][1], af[mi][2], af[mi][3], a);
            }
            #pragma unroll
            for (int np = 0; np < 2; np++) {
                unsigned a = bS + (unsigned)(wn + np * 16 + lrow) * RSTRIDE + kb;
                unsigned r0, r1, r2, r3;
                LDSM4(r0, r1, r2, r3, a);
                bf[2 * np][0] = r0; bf[2 * np + 1][0] = r1;
                bf[2 * np][1] = r2; bf[2 * np + 1][1] = r3;
            }
            #pragma unroll
            for (int mi = 0; mi < 4; mi++)
                #pragma unroll
                for (int ni = 0; ni < 4; ni++) {
                    asm volatile(
                        "mma.sync.aligned.m16n8k16.row.col.f32.bf16.bf16.f32 "
                        "{%0,%1,%2,%3}, {%4,%5,%6,%7}, {%8,%9}, {%0,%1,%2,%3};\n"
                        : "+f"(c[mi][ni][0]), "+f"(c[mi][ni][1]),
                          "+f"(c[mi][ni][2]), "+f"(c[mi][ni][3])
                        : "r"(af[mi][0]), "r"(af[mi][1]), "r"(af[mi][2]), "r"(af[mi][3]),
                          "r"(bf[ni][0]), "r"(bf[ni][1]));
                }
        }
    }

    #pragma unroll
    for (int ni = 0; ni < 4; ni++) {
        const int n0 = bn + wn + ni * 8 + tig * 2;
        const float bb0 = bih[n0], bb1 = bih[n0 + 1];
        #pragma unroll
        for (int mi = 0; mi < 4; mi++) {
            const int m0 = bm + wm + mi * 16 + gid;
            if (m0 < BB * TT) {
                float2 v = make_float2(c[mi][ni][0] + bb0, c[mi][ni][1] + bb1);
                *(float2*)(g_gx + (size_t)m0 * G3 + n0) = v;
            }
            if (m0 + 8 < BB * TT) {
                float2 v = make_float2(c[mi][ni][2] + bb0, c[mi][ni][3] + bb1);
                *(float2*)(g_gx + (size_t)(m0 + 8) * G3 + n0) = v;
            }
        }
    }
}

// =====================================================================
// software grid barrier (validated)
// =====================================================================
__device__ __forceinline__ void grid_barrier(int e, int bid) {
    __syncthreads();
    if (threadIdx.x == 0) {
        __threadfence();
        int g = (bid & 7) * 32;
        int v = atomicAdd(&g_cnt[g], 1);
        if (v == (GRU_BLOCKS / 8) - 1) {
            atomicExch(&g_cnt[g], 0);
            int m = atomicAdd(&g_master, 1);
            if (m == 7) {
                atomicExch(&g_master, 0);
                __threadfence();
                g_epoch = e;
            }
        }
        while (g_epoch < e) { }
        __threadfence();
    }
    __syncthreads();
}

// =====================================================================
// persistent GRU v3: Whh SMEM-RESIDENT as FP16 (10-bit mantissa; the
// bf16 version failed the gate at 1.02e-3 — fp16 cuts the recurrent
// quantization term ~8x). Same validated 128x12 geometry as R14.
// smem: 12x3x1536 fp16 weights (108KB) + 6144-float h buffer (24KB).
// =====================================================================
#define W_SMEM  (GRU_THREADS / 32 * 3 * HID)             // fp16 elements
#define GRU_SMEM (W_SMEM * 2 + BB * HID * 4)             // 110592 + 24576 B

__global__ __launch_bounds__(GRU_THREADS, 1) void k_gru_persist(
    const float* __restrict__ Whh, const float* __restrict__ bhh,
    const float* __restrict__ gx, float* __restrict__ out)
{
    extern __shared__ __align__(16) char gsm[];
    __half* wsm = (__half*)gsm;                          // [warp][gate][k]
    float* hs = (float*)(gsm + W_SMEM * 2);              // [b][k]

    const int tid = threadIdx.x;
    const int lane = tid & 31, warp = tid >> 5;
    const int bid = blockIdx.x;
    const int j = bid * 12 + warp;

    // ---- one-time: this warp's 3 weight rows -> fp16 smem ----
    #pragma unroll
    for (int g = 0; g < 3; g++) {
        const float* src = Whh + (size_t)(g * HID + j) * HID;
        __half* dst = wsm + (warp * 3 + g) * HID;
        for (int k = lane * 4; k < HID; k += 128) {
            float4 v = *(const float4*)(src + k);
            __half2 p0 = __floats2half2_rn(v.x, v.y);
            __half2 p1 = __floats2half2_rn(v.z, v.w);
            *(__half2*)(dst + k)     = p0;
            *(__half2*)(dst + k + 2) = p1;
        }
    }
    const float bhr = bhh[j], bhz = bhh[HID + j], bhn = bhh[2 * HID + j];
    const int c = j / FF, f = j - c * FF;
    const __half2* wr2 = (const __half2*)(wsm + (warp * 3 + 0) * HID);
    const __half2* wz2 = (const __half2*)(wsm + (warp * 3 + 1) * HID);
    const __half2* wn2 = (const __half2*)(wsm + (warp * 3 + 2) * HID);
    __syncthreads();

    for (int t = 0; t < TT; t++) {
        // stage h_{t-1} into smem
        const float4* hp4 = (const float4*)g_h[t & 1];
        float4* hs4 = (float4*)hs;
        #pragma unroll
        for (int i = 0; i < 4; i++) hs4[tid + i * GRU_THREADS] = hp4[tid + i * GRU_THREADS];
        __syncthreads();

        float ar[4] = {0.f,0.f,0.f,0.f};
        float az[4] = {0.f,0.f,0.f,0.f};
        float an[4] = {0.f,0.f,0.f,0.f};

        #pragma unroll 4
        for (int k = lane; k < HID / 4; k += 32) {
            float2 r01 = __half22float2(wr2[2 * k]);
            float2 r23 = __half22float2(wr2[2 * k + 1]);
            float2 z01 = __half22float2(wz2[2 * k]);
            float2 z23 = __half22float2(wz2[2 * k + 1]);
            float2 n01 = __half22float2(wn2[2 * k]);
            float2 n23 = __half22float2(wn2[2 * k + 1]);
            #pragma unroll
            for (int b = 0; b < 4; b++) {
                float4 h4 = hs4[b * (HID / 4) + k];
                ar[b] += r01.x * h4.x + r01.y * h4.y + r23.x * h4.z + r23.y * h4.w;
                az[b] += z01.x * h4.x + z01.y * h4.y + z23.x * h4.z + z23.y * h4.w;
                an[b] += n01.x * h4.x + n01.y * h4.y + n23.x * h4.z + n23.y * h4.w;
            }
        }
        #pragma unroll
        for (int off = 16; off; off >>= 1) {
            #pragma unroll
            for (int b = 0; b < 4; b++) {
                ar[b] += __shfl_xor_sync(0xffffffffu, ar[b], off);
                az[b] += __shfl_xor_sync(0xffffffffu, az[b], off);
                an[b] += __shfl_xor_sync(0xffffffffu, an[b], off);
            }
        }

        if (lane < 4) {
            const int b = lane;
            float sr, sz, sn;
            if      (b == 0) { sr = ar[0]; sz = az[0]; sn = an[0]; }
            else if (b == 1) { sr = ar[1]; sz = az[1]; sn = an[1]; }
            else if (b == 2) { sr = ar[2]; sz = az[2]; sn = an[2]; }
            else             { sr = ar[3]; sz = az[3]; sn = an[3]; }

            float ghr = sr + bhr;
            float ghz = sz + bhz;
            float ghn = sn + bhn;

            size_t gxb = ((size_t)b * TT + t) * G3;
            float r = 1.f / (1.f + expf(-(gx[gxb + j]           + ghr)));
            float z = 1.f / (1.f + expf(-(gx[gxb + HID + j]     + ghz)));
            float n = tanhf(      gx[gxb + 2 * HID + j] + r * ghn);
            float hp = hs[b * HID + j];
            float hn = (1.f - z) * n + z * hp;

            g_h[(t + 1) & 1][b * HID + j] = hn;
            out[(((size_t)b * CC + c) * TT + t) * FF + f] = hn;
            if (t == TT - 1) out[(size_t)BB * CC * TT * FF + b * HID + j] = hn;
        }

        grid_barrier(t + 1, bid);
    }
}

// =====================================================================
extern "C" void kernel_launch(void* const* d_in, const int* in_sizes, int n_in,
                              void* d_out, int out_size)
{
    const float* x   = (const float*)d_in[0];
    const float* h0  = (const float*)d_in[1];
    const float* Wq  = (const float*)d_in[2];
    const float* bq  = (const float*)d_in[3];
    const float* Wk  = (const float*)d_in[4];
    const float* bk  = (const float*)d_in[5];
    const float* Wv  = (const float*)d_in[6];
    const float* bv  = (const float*)d_in[7];
    const float* Wih = (const float*)d_in[8];
    const float* Whh = (const float*)d_in[9];
    const float* bih = (const float*)d_in[10];
    const float* bhh = (const float*)d_in[11];
    float* out = (float*)d_out;

    const int smem_attn = 38816 * (int)sizeof(float);   // ~152 KB
    cudaFuncSetAttribute(k_attn,        cudaFuncAttributeMaxDynamicSharedMemorySize, smem_attn);
    cudaFuncSetAttribute(k_gemm_bf,     cudaFuncAttributeMaxDynamicSharedMemorySize, GEMM_SMEM);
    cudaFuncSetAttribute(k_gru_persist, cudaFuncAttributeMaxDynamicSharedMemorySize, GRU_SMEM);

    float* gxp = nullptr;
    cudaGetSymbolAddress((void**)&gxp, g_gx);

    k_init<<<(BB * HID + 255) / 256, 256>>>(h0);
    k_cvt<<<1024, 256>>>(Wih);
    k_attn<<<dim3(TT, BB), 256, smem_attn>>>(x, Wq, bq, Wk, bk, Wv, bv);
    k_gemm_bf<<<dim3(G3 / 128, (BB * TT + 127) / 128), 256, GEMM_SMEM>>>(bih);
    k_gru_persist<<<GRU_BLOCKS, GRU_THREADS, GRU_SMEM>>>(Whh, bhh, gxp, out);
}